// round 11
// baseline (speedup 1.0000x reference)
#include <cuda_runtime.h>
#include <stdint.h>

#define QBINS 313
#define HWC   9216           // 96*96
#define MTOT  294912
#define TPB   128
#define PPT   2
#define NBLK  (MTOT / (TPB * PPT))   // 1152 = 8 CTAs/SM exactly (single wave)
#define GDIM  16
#define NCELL (GDIM * GDIM)
#define MAXC  64

__device__ unsigned short g_list[NCELL * MAXC];
__device__ int            g_cnt[NCELL];
__device__ float          g_partial[NBLK];
__device__ unsigned       g_count = 0;

typedef unsigned long long u64;
typedef unsigned int       u32;

// ---- packed f32x2 helpers (Blackwell FFMA2 path) ----
__device__ __forceinline__ u64 pk(float a, float b) {
    u64 r; asm("mov.b64 %0,{%1,%2};" : "=l"(r) : "f"(a), "f"(b)); return r;
}
__device__ __forceinline__ void upkf(u64 v, float& a, float& b) {
    asm("mov.b64 {%0,%1},%2;" : "=f"(a), "=f"(b) : "l"(v));
}
__device__ __forceinline__ void upki(u64 v, u32& a, u32& b) {
    asm("mov.b64 {%0,%1},%2;" : "=r"(a), "=r"(b) : "l"(v));
}
__device__ __forceinline__ u64 pki(u32 a, u32 b) {
    u64 r; asm("mov.b64 %0,{%1,%2};" : "=l"(r) : "r"(a), "r"(b)); return r;
}
__device__ __forceinline__ u64 f2mul(u64 a, u64 b) {
    u64 r; asm("mul.rn.f32x2 %0,%1,%2;" : "=l"(r) : "l"(a), "l"(b)); return r;
}
__device__ __forceinline__ u64 f2add(u64 a, u64 b) {
    u64 r; asm("add.rn.f32x2 %0,%1,%2;" : "=l"(r) : "l"(a), "l"(b)); return r;
}
__device__ __forceinline__ u64 f2fma(u64 a, u64 b, u64 c) {
    u64 r; asm("fma.rn.f32x2 %0,%1,%2,%3;" : "=l"(r) : "l"(a), "l"(b), "l"(c)); return r;
}

// sorted top-5 insert, uint keys (9 IMNMX)
__device__ __forceinline__ void ins5(u32& k0, u32& k1, u32& k2, u32& k3, u32& k4, u32 key) {
    u32 lo, hi;
    k4 = min(k4, key);
    lo = min(k3, k4); hi = max(k3, k4); k3 = lo; k4 = hi;
    lo = min(k2, k3); hi = max(k2, k3); k2 = lo; k3 = hi;
    lo = min(k1, k2); hi = max(k1, k2); k1 = lo; k2 = hi;
    lo = min(k0, k1); hi = max(k0, k1); k0 = lo; k1 = hi;
}

// sorted top-5 insert, float distances (9 FMNMX)
__device__ __forceinline__ void ins5f(float& d0, float& d1, float& d2, float& d3, float& d4, float d) {
    float lo, hi;
    d4 = fminf(d4, d);
    lo = fminf(d3, d4); hi = fmaxf(d3, d4); d3 = lo; d4 = hi;
    lo = fminf(d2, d3); hi = fmaxf(d2, d3); d2 = lo; d3 = hi;
    lo = fminf(d1, d2); hi = fmaxf(d1, d2); d1 = lo; d2 = hi;
    lo = fminf(d0, d1); hi = fmaxf(d0, d1); d0 = lo; d1 = hi;
}

// ---- precompute: per-cell candidate lists, warp per cell ----
// cell side 16, half-diag 11.314: c in top-5 of any p in cell => |c-cc| <= d5(cc)+2r.
__global__ void build_grid(const float* __restrict__ centers) {
    __shared__ float2 sc[QBINS];
    for (int i = threadIdx.x; i < QBINS; i += blockDim.x)
        sc[i] = reinterpret_cast<const float2*>(centers)[i];
    __syncthreads();

    const int lane = threadIdx.x & 31;
    const int cell = (blockIdx.x * blockDim.x + threadIdx.x) >> 5;
    if (cell >= NCELL) return;
    const int cy = cell >> 4, cx = cell & 15;
    const float cca = -120.f + 16.f * cx;
    const float ccb = -120.f + 16.f * cy;

    float d0 = 3.4e38f, d1 = 3.4e38f, d2 = 3.4e38f, d3 = 3.4e38f, d4 = 3.4e38f;
    for (int q = lane; q < QBINS; q += 32) {
        float da = cca - sc[q].x, db = ccb - sc[q].y;
        ins5f(d0, d1, d2, d3, d4, fmaf(da, da, db * db));
    }
    #pragma unroll
    for (int off = 16; off > 0; off >>= 1) {
        float e0 = __shfl_xor_sync(0xFFFFFFFFu, d0, off);
        float e1 = __shfl_xor_sync(0xFFFFFFFFu, d1, off);
        float e2 = __shfl_xor_sync(0xFFFFFFFFu, d2, off);
        float e3 = __shfl_xor_sync(0xFFFFFFFFu, d3, off);
        float e4 = __shfl_xor_sync(0xFFFFFFFFu, d4, off);
        ins5f(d0, d1, d2, d3, d4, e0);
        ins5f(d0, d1, d2, d3, d4, e1);
        ins5f(d0, d1, d2, d3, d4, e2);
        ins5f(d0, d1, d2, d3, d4, e3);
        ins5f(d0, d1, d2, d3, d4, e4);
    }
    const float R  = sqrtf(d4) + 22.6275f + 0.01f;   // d5(cc) + 2r (+eps)
    const float R2 = R * R;

    int base = 0;
    for (int r = 0; r * 32 < QBINS; ++r) {
        int q = r * 32 + lane;
        bool pred = false;
        if (q < QBINS) {
            float da = cca - sc[q].x, db = ccb - sc[q].y;
            pred = fmaf(da, da, db * db) <= R2;
        }
        u32 mask = __ballot_sync(0xFFFFFFFFu, pred);
        int pos = base + __popc(mask & ((1u << lane) - 1u));
        if (pred && pos < MAXC) g_list[cell * MAXC + pos] = (unsigned short)q;
        base += __popc(mask);
    }
    if (lane == 0) g_cnt[cell] = min(base, MAXC);
}

// per-pixel selection + soft-encode + gather -> (coef, pre): part = coef*log(S) + pre
__device__ __forceinline__ void pixel_prep(float a, float bb, const float* __restrict__ gb,
                                           const float4* __restrict__ s_c,
                                           float& coef, float& pre)
{
    const float up = fmaf(0.5f * a, a, fmaf(0.5f * bb, bb, 0.5f));
    int cx = min(max((int)floorf((a  + 128.f) * 0.0625f), 0), GDIM - 1);
    int cy = min(max((int)floorf((bb + 128.f) * 0.0625f), 0), GDIM - 1);
    int cell = cy * GDIM + cx;
    int n = g_cnt[cell];
    const unsigned short* lst = g_list + cell * MAXC;

    u32 k0 = 0xFFFFFFFFu, k1 = 0xFFFFFFFFu, k2 = 0xFFFFFFFFu,
        k3 = 0xFFFFFFFFu, k4 = 0xFFFFFFFFu;
    for (int j = 0; j < n; ++j) {
        int q = lst[j];
        float4 c = s_c[q];
        float e = fmaf(-a, c.x, fmaf(-bb, c.y, c.z)) + up;   // d2/2 + 0.5
        ins5(k0, k1, k2, k3, k4, (__float_as_uint(e) & 0xFFFFFE00u) | (u32)q);
    }

    u32 kk[5] = {k0, k1, k2, k3, k4};
    float wk[5];
    int   idx[5];
    float wsum = 0.f;
    #pragma unroll
    for (int j = 0; j < 5; ++j) {
        idx[j] = (int)(kk[j] & 511u);
        float4 c = s_c[idx[j]];
        float da = a - c.x;
        float db = bb - c.y;
        float d2 = fmaf(da, da, db * db);
        float w  = __expf(-0.02f * d2);     // exp(-d2/(2*sigma^2)), sigma=5
        wk[j] = w;
        wsum += w;
    }
    float inv = 1.0f / (wsum + 1e-8f);
    float dot = 0.f;
    #pragma unroll
    for (int j = 0; j < 5; ++j) {
        float x = __ldg(gb + (size_t)idx[j] * HWC);
        dot = fmaf(wk[j], x, dot);
    }
    float pw = s_c[k0 & 511u].w;
    coef = (wsum * inv) * pw;
    pre  = -(dot * inv) * pw;
}

__global__ void __launch_bounds__(TPB, 8)
loss_main(const float* __restrict__ pred,      // (B, Q, H, W)
          const float* __restrict__ tgt,       // (B, 2, H, W)
          const float* __restrict__ centers,   // (Q, 2)
          const float* __restrict__ cw,        // (Q,)
          float* __restrict__ out)
{
    __shared__ float4 s_c[QBINS];     // (cx, cy, |c|^2/2, class_weight)
    __shared__ float  s_red[TPB / 32];
    __shared__ float  s_fin[TPB];
    __shared__ bool   s_last;

    const int tid = threadIdx.x;
    for (int i = tid; i < QBINS; i += TPB) {
        float2 c = reinterpret_cast<const float2*>(centers)[i];
        float h = fmaf(0.5f * c.x, c.x, 0.5f * c.y * c.y);
        s_c[i] = make_float4(c.x, c.y, h, cw[i]);
    }
    __syncthreads();

    const int m0  = (blockIdx.x * TPB + tid) * PPT;   // two adjacent pixels
    const int b   = m0 / HWC;                         // block = 256 contiguous pixels, same b
    const int rem = m0 - b * HWC;

    const float2 av = *reinterpret_cast<const float2*>(tgt + (size_t)(2 * b)     * HWC + rem);
    const float2 bv = *reinterpret_cast<const float2*>(tgt + (size_t)(2 * b + 1) * HWC + rem);

    const float* gb = pred + (size_t)b * QBINS * HWC + rem;

    float coef0, pre0, coef1, pre1;
    pixel_prep(av.x * 128.f, bv.x * 128.f, gb,     s_c, coef0, pre0);
    pixel_prep(av.y * 128.f, bv.y * 128.f, gb + 1, s_c, coef1, pre1);

    // exp2 constants (degree-4; rel err <= ~4e-5, budget 1e-3 — validated R8/R9)
    const u64 L2E = pk(1.4426950408889634f, 1.4426950408889634f);
    const u64 CB  = pk(12582912.0f, 12582912.0f);
    const u64 CNB = pk(-12582912.0f, -12582912.0f);
    const u64 M1  = pk(-1.0f, -1.0f);
    const u64 C4  = pk(9.6181291076e-3f, 9.6181291076e-3f);
    const u64 C3  = pk(5.5504108665e-2f, 5.5504108665e-2f);
    const u64 C2  = pk(2.4022650696e-1f, 2.4022650696e-1f);
    const u64 C1  = pk(6.9314718056e-1f, 6.9314718056e-1f);
    const u64 C0  = pk(1.0f, 1.0f);

    const float2* p2 = reinterpret_cast<const float2*>(gb);

    // ---- pure streaming softmax denominators (proven best shape: unroll 8, float2) ----
    u64 S01 = 0ull;
    #pragma unroll 8
    for (int q = 0; q < QBINS; ++q) {
        float2 v = __ldcs(p2 + (size_t)q * (HWC / 2));
        u64 T = f2mul(pk(v.x, v.y), L2E);
        u64 Z = f2add(T, CB);
        u64 W = f2add(Z, CNB);               // rint(t)
        u64 R = f2fma(W, M1, T);             // t - rint(t), in [-0.5,0.5]
        u64 P = f2fma(C4, R, C3);
        P = f2fma(P, R, C2);
        P = f2fma(P, R, C1);
        P = f2fma(P, R, C0);
        u32 zi0, zi1, pi0, pi1;
        upki(Z, zi0, zi1); upki(P, pi0, pi1);
        S01 = f2add(S01, pki(pi0 + (zi0 << 23), pi1 + (zi1 << 23)));
    }
    float S0, S1;
    upkf(S01, S0, S1);

    float part = fmaf(coef0, __logf(S0), pre0) + fmaf(coef1, __logf(S1), pre1);

    // ---- deterministic block reduction ----
    const int lane = tid & 31, wid = tid >> 5;
    #pragma unroll
    for (int o = 16; o > 0; o >>= 1)
        part += __shfl_down_sync(0xFFFFFFFFu, part, o);
    if (lane == 0) s_red[wid] = part;
    __syncthreads();

    if (tid == 0) {
        float bsum = 0.f;
        #pragma unroll
        for (int w = 0; w < TPB / 32; ++w) bsum += s_red[w];
        g_partial[blockIdx.x] = bsum;
        __threadfence();
        unsigned t = atomicAdd(&g_count, 1u);
        s_last = (t == NBLK - 1);
    }
    __syncthreads();

    if (s_last) {
        float v = 0.f;
        #pragma unroll
        for (int base = 0; base < NBLK; base += TPB)
            v += g_partial[base + tid];
        s_fin[tid] = v;
        __syncthreads();
        #pragma unroll
        for (int s = TPB / 2; s > 0; s >>= 1) {
            if (tid < s) s_fin[tid] += s_fin[tid + s];
            __syncthreads();
        }
        if (tid == 0) {
            out[0] = s_fin[0] * (1.0f / (float)MTOT);
            g_count = 0;   // reset for next graph replay
        }
    }
}

extern "C" void kernel_launch(void* const* d_in, const int* in_sizes, int n_in,
                              void* d_out, int out_size) {
    const float* pred    = (const float*)d_in[0];   // (32,313,96,96)
    const float* tgt     = (const float*)d_in[1];   // (32,2,96,96)
    const float* centers = (const float*)d_in[2];   // (313,2)
    const float* cw      = (const float*)d_in[3];   // (313,)
    (void)in_sizes; (void)n_in; (void)out_size;

    build_grid<<<(NCELL * 32 + 255) / 256, 256>>>(centers);
    loss_main<<<NBLK, TPB>>>(pred, tgt, centers, cw, (float*)d_out);
}

// round 13
// speedup vs baseline: 1.1341x; 1.1341x over previous
#include <cuda_runtime.h>
#include <stdint.h>

#define QBINS 313
#define HWC   9216           // 96*96
#define MTOT  294912
#define TPB   128
#define PPT   4
#define NBLK  (MTOT / (TPB * PPT))   // 576
#define GDIM  32
#define NCELL (GDIM * GDIM)
#define MAXC  64

__device__ unsigned short g_list[NCELL * MAXC];
__device__ int            g_cnt[NCELL];
__device__ float          g_partial[NBLK];
__device__ unsigned       g_count = 0;

typedef unsigned long long u64;
typedef unsigned int       u32;

// ---- packed f32x2 helpers (Blackwell FFMA2 path) ----
__device__ __forceinline__ u64 pk(float a, float b) {
    u64 r; asm("mov.b64 %0,{%1,%2};" : "=l"(r) : "f"(a), "f"(b)); return r;
}
__device__ __forceinline__ void upkf(u64 v, float& a, float& b) {
    asm("mov.b64 {%0,%1},%2;" : "=f"(a), "=f"(b) : "l"(v));
}
__device__ __forceinline__ void upki(u64 v, u32& a, u32& b) {
    asm("mov.b64 {%0,%1},%2;" : "=r"(a), "=r"(b) : "l"(v));
}
__device__ __forceinline__ u64 pki(u32 a, u32 b) {
    u64 r; asm("mov.b64 %0,{%1,%2};" : "=l"(r) : "r"(a), "r"(b)); return r;
}
__device__ __forceinline__ u64 f2mul(u64 a, u64 b) {
    u64 r; asm("mul.rn.f32x2 %0,%1,%2;" : "=l"(r) : "l"(a), "l"(b)); return r;
}
__device__ __forceinline__ u64 f2add(u64 a, u64 b) {
    u64 r; asm("add.rn.f32x2 %0,%1,%2;" : "=l"(r) : "l"(a), "l"(b)); return r;
}
__device__ __forceinline__ u64 f2fma(u64 a, u64 b, u64 c) {
    u64 r; asm("fma.rn.f32x2 %0,%1,%2,%3;" : "=l"(r) : "l"(a), "l"(b), "l"(c)); return r;
}

// sorted top-5 insert, uint keys (9 IMNMX)
__device__ __forceinline__ void ins5(u32& k0, u32& k1, u32& k2, u32& k3, u32& k4, u32 key) {
    u32 lo, hi;
    k4 = min(k4, key);
    lo = min(k3, k4); hi = max(k3, k4); k3 = lo; k4 = hi;
    lo = min(k2, k3); hi = max(k2, k3); k2 = lo; k3 = hi;
    lo = min(k1, k2); hi = max(k1, k2); k1 = lo; k2 = hi;
    lo = min(k0, k1); hi = max(k0, k1); k0 = lo; k1 = hi;
}

// sorted top-5 insert, float distances (9 FMNMX)
__device__ __forceinline__ void ins5f(float& d0, float& d1, float& d2, float& d3, float& d4, float d) {
    float lo, hi;
    d4 = fminf(d4, d);
    lo = fminf(d3, d4); hi = fmaxf(d3, d4); d3 = lo; d4 = hi;
    lo = fminf(d2, d3); hi = fmaxf(d2, d3); d2 = lo; d3 = hi;
    lo = fminf(d1, d2); hi = fmaxf(d1, d2); d1 = lo; d2 = hi;
    lo = fminf(d0, d1); hi = fmaxf(d0, d1); d0 = lo; d1 = hi;
}

// ---- precompute: per-cell candidate lists, warp per cell ----
// cell side 8, half-diag r=5.657: c in top-5 of any p in cell => |c-cc| <= d5(cc)+2r.
__global__ void build_grid(const float* __restrict__ centers) {
    __shared__ float2 sc[QBINS];
    for (int i = threadIdx.x; i < QBINS; i += blockDim.x)
        sc[i] = reinterpret_cast<const float2*>(centers)[i];
    __syncthreads();

    const int lane = threadIdx.x & 31;
    const int cell = (blockIdx.x * blockDim.x + threadIdx.x) >> 5;   // warp id = cell
    if (cell >= NCELL) return;
    const int cy = cell >> 5, cx = cell & 31;
    const float cca = -124.f + 8.f * cx;
    const float ccb = -124.f + 8.f * cy;

    float d0 = 3.4e38f, d1 = 3.4e38f, d2 = 3.4e38f, d3 = 3.4e38f, d4 = 3.4e38f;
    for (int q = lane; q < QBINS; q += 32) {
        float da = cca - sc[q].x, db = ccb - sc[q].y;
        ins5f(d0, d1, d2, d3, d4, fmaf(da, da, db * db));
    }
    #pragma unroll
    for (int off = 16; off > 0; off >>= 1) {
        float e0 = __shfl_xor_sync(0xFFFFFFFFu, d0, off);
        float e1 = __shfl_xor_sync(0xFFFFFFFFu, d1, off);
        float e2 = __shfl_xor_sync(0xFFFFFFFFu, d2, off);
        float e3 = __shfl_xor_sync(0xFFFFFFFFu, d3, off);
        float e4 = __shfl_xor_sync(0xFFFFFFFFu, d4, off);
        ins5f(d0, d1, d2, d3, d4, e0);
        ins5f(d0, d1, d2, d3, d4, e1);
        ins5f(d0, d1, d2, d3, d4, e2);
        ins5f(d0, d1, d2, d3, d4, e3);
        ins5f(d0, d1, d2, d3, d4, e4);
    }
    const float R  = sqrtf(d4) + 11.3138f + 0.01f;   // d5(cc) + 2r (+eps)
    const float R2 = R * R;

    int base = 0;
    for (int r = 0; r * 32 < QBINS; ++r) {
        int q = r * 32 + lane;
        bool pred = false;
        if (q < QBINS) {
            float da = cca - sc[q].x, db = ccb - sc[q].y;
            pred = fmaf(da, da, db * db) <= R2;
        }
        u32 mask = __ballot_sync(0xFFFFFFFFu, pred);
        int pos = base + __popc(mask & ((1u << lane) - 1u));
        if (pred && pos < MAXC) g_list[cell * MAXC + pos] = (unsigned short)q;
        base += __popc(mask);
    }
    if (lane == 0) g_cnt[cell] = min(base, MAXC);
}

// per-pixel selection + soft-encode epilogue -> (coef, pre):  part = coef*log(S) + pre
__device__ __forceinline__ void pixel_prep(float a, float bb, const float* __restrict__ gb,
                                           const float4* __restrict__ s_c,
                                           float& coef, float& pre)
{
    const float up = fmaf(0.5f * a, a, fmaf(0.5f * bb, bb, 0.5f));
    int cx = min(max((int)floorf((a  + 128.f) * 0.125f), 0), GDIM - 1);
    int cy = min(max((int)floorf((bb + 128.f) * 0.125f), 0), GDIM - 1);
    int cell = cy * GDIM + cx;
    int n = g_cnt[cell];
    const unsigned short* lst = g_list + cell * MAXC;

    u32 k0 = 0xFFFFFFFFu, k1 = 0xFFFFFFFFu, k2 = 0xFFFFFFFFu,
        k3 = 0xFFFFFFFFu, k4 = 0xFFFFFFFFu;
    for (int j = 0; j < n; ++j) {
        int q = lst[j];
        float4 c = s_c[q];
        float e = fmaf(-a, c.x, fmaf(-bb, c.y, c.z)) + up;   // d2/2 + 0.5
        ins5(k0, k1, k2, k3, k4, (__float_as_uint(e) & 0xFFFFFE00u) | (u32)q);
    }

    u32 kk[5] = {k0, k1, k2, k3, k4};
    float wk[5];
    int   idx[5];
    float wsum = 0.f;
    #pragma unroll
    for (int j = 0; j < 5; ++j) {
        idx[j] = (int)(kk[j] & 511u);
        float4 c = s_c[idx[j]];
        float da = a - c.x;
        float db = bb - c.y;
        float d2 = fmaf(da, da, db * db);
        float w  = __expf(-0.02f * d2);     // exp(-d2/(2*sigma^2)), sigma=5
        wk[j] = w;
        wsum += w;
    }
    float inv = 1.0f / (wsum + 1e-8f);
    float dot = 0.f;
    #pragma unroll
    for (int j = 0; j < 5; ++j) {
        float x = __ldg(gb + (size_t)idx[j] * HWC);
        dot = fmaf(wk[j], x, dot);
    }
    float pw = s_c[k0 & 511u].w;
    coef = (wsum * inv) * pw;
    pre  = -(dot * inv) * pw;
}

struct ExpC {
    u64 L2E, CB, CNB, M1, C5, C4, C3, C2, C1, C0;
};

__device__ __forceinline__ void expacc(float4 v, u64& S01, u64& S23, const ExpC& K) {
    {
        u64 T = f2mul(pk(v.x, v.y), K.L2E);
        u64 Z = f2add(T, K.CB);
        u64 W = f2add(Z, K.CNB);
        u64 R = f2fma(W, K.M1, T);
        u64 P = f2fma(K.C5, R, K.C4);
        P = f2fma(P, R, K.C3);
        P = f2fma(P, R, K.C2);
        P = f2fma(P, R, K.C1);
        P = f2fma(P, R, K.C0);
        u32 zi0, zi1, pi0, pi1;
        upki(Z, zi0, zi1); upki(P, pi0, pi1);
        S01 = f2add(S01, pki(pi0 + (zi0 << 23), pi1 + (zi1 << 23)));
    }
    {
        u64 T = f2mul(pk(v.z, v.w), K.L2E);
        u64 Z = f2add(T, K.CB);
        u64 W = f2add(Z, K.CNB);
        u64 R = f2fma(W, K.M1, T);
        u64 P = f2fma(K.C5, R, K.C4);
        P = f2fma(P, R, K.C3);
        P = f2fma(P, R, K.C2);
        P = f2fma(P, R, K.C1);
        P = f2fma(P, R, K.C0);
        u32 zi0, zi1, pi0, pi1;
        upki(Z, zi0, zi1); upki(P, pi0, pi1);
        S23 = f2add(S23, pki(pi0 + (zi0 << 23), pi1 + (zi1 << 23)));
    }
}

__global__ void __launch_bounds__(TPB, 4)
loss_main(const float* __restrict__ pred,      // (B, Q, H, W)
          const float* __restrict__ tgt,       // (B, 2, H, W)
          const float* __restrict__ centers,   // (Q, 2)
          const float* __restrict__ cw,        // (Q,)
          float* __restrict__ out)
{
    __shared__ float4 s_c[QBINS];     // (cx, cy, |c|^2/2, class_weight)
    __shared__ float  s_red[TPB / 32];
    __shared__ float  s_fin[TPB];
    __shared__ bool   s_last;

    const int tid = threadIdx.x;
    for (int i = tid; i < QBINS; i += TPB) {
        float2 c = reinterpret_cast<const float2*>(centers)[i];
        float h = fmaf(0.5f * c.x, c.x, 0.5f * c.y * c.y);
        s_c[i] = make_float4(c.x, c.y, h, cw[i]);
    }
    __syncthreads();

    const int m0  = (blockIdx.x * TPB + tid) * PPT;   // four adjacent pixels
    const int b   = m0 / HWC;                         // block = 512 contiguous pixels, same b
    const int rem = m0 - b * HWC;

    const float4 av = *reinterpret_cast<const float4*>(tgt + (size_t)(2 * b)     * HWC + rem);
    const float4 bv = *reinterpret_cast<const float4*>(tgt + (size_t)(2 * b + 1) * HWC + rem);
    const float aa[4] = {av.x * 128.f, av.y * 128.f, av.z * 128.f, av.w * 128.f};
    const float bb[4] = {bv.x * 128.f, bv.y * 128.f, bv.z * 128.f, bv.w * 128.f};

    const float* gb = pred + (size_t)b * QBINS * HWC + rem;

    float coef[4], pre[4];
    #pragma unroll
    for (int p = 0; p < 4; ++p)
        pixel_prep(aa[p], bb[p], gb + p, s_c, coef[p], pre[p]);

    ExpC K;
    K.L2E = pk(1.4426950408889634f, 1.4426950408889634f);
    K.CB  = pk(12582912.0f, 12582912.0f);
    K.CNB = pk(-12582912.0f, -12582912.0f);
    K.M1  = pk(-1.0f, -1.0f);
    K.C5  = pk(1.3333558146e-3f, 1.3333558146e-3f);
    K.C4  = pk(9.6181291076e-3f, 9.6181291076e-3f);
    K.C3  = pk(5.5504108665e-2f, 5.5504108665e-2f);
    K.C2  = pk(2.4022650696e-1f, 2.4022650696e-1f);
    K.C1  = pk(6.9314718056e-1f, 6.9314718056e-1f);
    K.C0  = pk(1.0f, 1.0f);

    // ---- streaming softmax denominators, explicit 2-stage prefetch pipeline ----
    const float4* p4 = reinterpret_cast<const float4*>(gb);
    u64 S01 = 0ull, S23 = 0ull;

    float4 buf[4];
    #pragma unroll
    for (int j = 0; j < 4; ++j)
        buf[j] = __ldcs(p4 + (size_t)j * (HWC / 4));

    for (int base = 0; base <= 304; base += 4) {     // 77 iterations: q 0..307 processed
        float4 nxt[4];
        #pragma unroll
        for (int j = 0; j < 4; ++j)
            nxt[j] = __ldcs(p4 + (size_t)(base + 4 + j) * (HWC / 4));
        #pragma unroll
        for (int j = 0; j < 4; ++j)
            expacc(buf[j], S01, S23, K);
        #pragma unroll
        for (int j = 0; j < 4; ++j)
            buf[j] = nxt[j];
    }
    #pragma unroll
    for (int j = 0; j < 4; ++j)                      // q 308..311
        expacc(buf[j], S01, S23, K);
    expacc(__ldcs(p4 + (size_t)312 * (HWC / 4)), S01, S23, K);   // q 312

    float S[4];
    upkf(S01, S[0], S[1]);
    upkf(S23, S[2], S[3]);

    float part = 0.f;
    #pragma unroll
    for (int p = 0; p < 4; ++p)
        part += fmaf(coef[p], __logf(S[p]), pre[p]);

    // ---- deterministic block reduction ----
    const int lane = tid & 31, wid = tid >> 5;
    #pragma unroll
    for (int o = 16; o > 0; o >>= 1)
        part += __shfl_down_sync(0xFFFFFFFFu, part, o);
    if (lane == 0) s_red[wid] = part;
    __syncthreads();

    if (tid == 0) {
        float bsum = 0.f;
        #pragma unroll
        for (int w = 0; w < TPB / 32; ++w) bsum += s_red[w];
        g_partial[blockIdx.x] = bsum;
        __threadfence();
        unsigned t = atomicAdd(&g_count, 1u);
        s_last = (t == NBLK - 1);
    }
    __syncthreads();

    if (s_last) {
        float v = 0.f;
        #pragma unroll
        for (int base = 0; base < NBLK; base += TPB)
            if (base + tid < NBLK) v += g_partial[base + tid];
        s_fin[tid] = v;
        __syncthreads();
        #pragma unroll
        for (int s = TPB / 2; s > 0; s >>= 1) {
            if (tid < s) s_fin[tid] += s_fin[tid + s];
            __syncthreads();
        }
        if (tid == 0) {
            out[0] = s_fin[0] * (1.0f / (float)MTOT);
            g_count = 0;   // reset for next graph replay
        }
    }
}

extern "C" void kernel_launch(void* const* d_in, const int* in_sizes, int n_in,
                              void* d_out, int out_size) {
    const float* pred    = (const float*)d_in[0];   // (32,313,96,96)
    const float* tgt     = (const float*)d_in[1];   // (32,2,96,96)
    const float* centers = (const float*)d_in[2];   // (313,2)
    const float* cw      = (const float*)d_in[3];   // (313,)
    (void)in_sizes; (void)n_in; (void)out_size;

    build_grid<<<(NCELL * 32) / 256, 256>>>(centers);
    loss_main<<<NBLK, TPB>>>(pred, tgt, centers, cw, (float*)d_out);
}

// round 14
// speedup vs baseline: 1.2526x; 1.1045x over previous
#include <cuda_runtime.h>
#include <stdint.h>

#define QBINS 313
#define HWC   9216           // 96*96
#define MTOT  294912
#define TPB   128
#define PPT   4
#define NBLK  (MTOT / (TPB * PPT))   // 576 (fully resident at 4 CTAs/SM)
#define GDIM  32
#define NCELL (GDIM * GDIM)          // 1024 cells = warps of CTAs 0..255
#define MAXC  64

__device__ unsigned short g_list[NCELL * MAXC];
__device__ int            g_cnt[NCELL];
__device__ float          g_partial[NBLK];
__device__ unsigned       g_count = 0;
__device__ unsigned       g_ready = 0;

typedef unsigned long long u64;
typedef unsigned int       u32;

// ---- packed f32x2 helpers (Blackwell FFMA2 path) ----
__device__ __forceinline__ u64 pk(float a, float b) {
    u64 r; asm("mov.b64 %0,{%1,%2};" : "=l"(r) : "f"(a), "f"(b)); return r;
}
__device__ __forceinline__ void upkf(u64 v, float& a, float& b) {
    asm("mov.b64 {%0,%1},%2;" : "=f"(a), "=f"(b) : "l"(v));
}
__device__ __forceinline__ void upki(u64 v, u32& a, u32& b) {
    asm("mov.b64 {%0,%1},%2;" : "=r"(a), "=r"(b) : "l"(v));
}
__device__ __forceinline__ u64 pki(u32 a, u32 b) {
    u64 r; asm("mov.b64 %0,{%1,%2};" : "=l"(r) : "r"(a), "r"(b)); return r;
}
__device__ __forceinline__ u64 f2mul(u64 a, u64 b) {
    u64 r; asm("mul.rn.f32x2 %0,%1,%2;" : "=l"(r) : "l"(a), "l"(b)); return r;
}
__device__ __forceinline__ u64 f2add(u64 a, u64 b) {
    u64 r; asm("add.rn.f32x2 %0,%1,%2;" : "=l"(r) : "l"(a), "l"(b)); return r;
}
__device__ __forceinline__ u64 f2fma(u64 a, u64 b, u64 c) {
    u64 r; asm("fma.rn.f32x2 %0,%1,%2,%3;" : "=l"(r) : "l"(a), "l"(b), "l"(c)); return r;
}

// sorted top-5 insert, uint keys (9 IMNMX)
__device__ __forceinline__ void ins5(u32& k0, u32& k1, u32& k2, u32& k3, u32& k4, u32 key) {
    u32 lo, hi;
    k4 = min(k4, key);
    lo = min(k3, k4); hi = max(k3, k4); k3 = lo; k4 = hi;
    lo = min(k2, k3); hi = max(k2, k3); k2 = lo; k3 = hi;
    lo = min(k1, k2); hi = max(k1, k2); k1 = lo; k2 = hi;
    lo = min(k0, k1); hi = max(k0, k1); k0 = lo; k1 = hi;
}

// sorted top-5 insert, float distances (9 FMNMX)
__device__ __forceinline__ void ins5f(float& d0, float& d1, float& d2, float& d3, float& d4, float d) {
    float lo, hi;
    d4 = fminf(d4, d);
    lo = fminf(d3, d4); hi = fmaxf(d3, d4); d3 = lo; d4 = hi;
    lo = fminf(d2, d3); hi = fmaxf(d2, d3); d2 = lo; d3 = hi;
    lo = fminf(d1, d2); hi = fmaxf(d1, d2); d1 = lo; d2 = hi;
    lo = fminf(d0, d1); hi = fmaxf(d0, d1); d0 = lo; d1 = hi;
}

// ---- builder: one warp builds one cell's candidate list (exact superset) ----
// cell side 8, half-diag r=5.657: c in top-5 of any p in cell => |c-cc| <= d5(cc)+2r.
__device__ __forceinline__ void build_cell(int cell, int lane, const float4* __restrict__ s_c) {
    const int cy = cell >> 5, cx = cell & 31;
    const float cca = -124.f + 8.f * cx;
    const float ccb = -124.f + 8.f * cy;

    float d0 = 3.4e38f, d1 = 3.4e38f, d2 = 3.4e38f, d3 = 3.4e38f, d4 = 3.4e38f;
    for (int q = lane; q < QBINS; q += 32) {
        float da = cca - s_c[q].x, db = ccb - s_c[q].y;
        ins5f(d0, d1, d2, d3, d4, fmaf(da, da, db * db));
    }
    #pragma unroll
    for (int off = 16; off > 0; off >>= 1) {
        float e0 = __shfl_xor_sync(0xFFFFFFFFu, d0, off);
        float e1 = __shfl_xor_sync(0xFFFFFFFFu, d1, off);
        float e2 = __shfl_xor_sync(0xFFFFFFFFu, d2, off);
        float e3 = __shfl_xor_sync(0xFFFFFFFFu, d3, off);
        float e4 = __shfl_xor_sync(0xFFFFFFFFu, d4, off);
        ins5f(d0, d1, d2, d3, d4, e0);
        ins5f(d0, d1, d2, d3, d4, e1);
        ins5f(d0, d1, d2, d3, d4, e2);
        ins5f(d0, d1, d2, d3, d4, e3);
        ins5f(d0, d1, d2, d3, d4, e4);
    }
    const float R  = sqrtf(d4) + 11.3138f + 0.01f;   // d5(cc) + 2r (+eps)
    const float R2 = R * R;

    int base = 0;
    for (int r = 0; r * 32 < QBINS; ++r) {
        int q = r * 32 + lane;
        bool pred = false;
        if (q < QBINS) {
            float da = cca - s_c[q].x, db = ccb - s_c[q].y;
            pred = fmaf(da, da, db * db) <= R2;
        }
        u32 mask = __ballot_sync(0xFFFFFFFFu, pred);
        int pos = base + __popc(mask & ((1u << lane) - 1u));
        if (pred && pos < MAXC) g_list[cell * MAXC + pos] = (unsigned short)q;
        base += __popc(mask);
    }
    if (lane == 0) g_cnt[cell] = min(base, MAXC);
}

// per-pixel selection + soft-encode + gather -> (coef, pre):  part = coef*log(S) + pre
__device__ __forceinline__ void pixel_prep(float a, float bb, const float* __restrict__ gb,
                                           const float4* __restrict__ s_c,
                                           float& coef, float& pre)
{
    const float up = fmaf(0.5f * a, a, fmaf(0.5f * bb, bb, 0.5f));
    int cx = min(max((int)floorf((a  + 128.f) * 0.125f), 0), GDIM - 1);
    int cy = min(max((int)floorf((bb + 128.f) * 0.125f), 0), GDIM - 1);
    int cell = cy * GDIM + cx;
    int n = g_cnt[cell];
    const unsigned short* lst = g_list + cell * MAXC;

    u32 k0 = 0xFFFFFFFFu, k1 = 0xFFFFFFFFu, k2 = 0xFFFFFFFFu,
        k3 = 0xFFFFFFFFu, k4 = 0xFFFFFFFFu;
    for (int j = 0; j < n; ++j) {
        int q = lst[j];
        float4 c = s_c[q];
        float e = fmaf(-a, c.x, fmaf(-bb, c.y, c.z)) + up;   // d2/2 + 0.5
        ins5(k0, k1, k2, k3, k4, (__float_as_uint(e) & 0xFFFFFE00u) | (u32)q);
    }

    u32 kk[5] = {k0, k1, k2, k3, k4};
    float wk[5];
    int   idx[5];
    float wsum = 0.f;
    #pragma unroll
    for (int j = 0; j < 5; ++j) {
        idx[j] = (int)(kk[j] & 511u);
        float4 c = s_c[idx[j]];
        float da = a - c.x;
        float db = bb - c.y;
        float d2 = fmaf(da, da, db * db);
        float w  = __expf(-0.02f * d2);     // exp(-d2/(2*sigma^2)), sigma=5
        wk[j] = w;
        wsum += w;
    }
    float inv = 1.0f / (wsum + 1e-8f);
    float dot = 0.f;
    #pragma unroll
    for (int j = 0; j < 5; ++j) {
        float x = __ldg(gb + (size_t)idx[j] * HWC);
        dot = fmaf(wk[j], x, dot);
    }
    float pw = s_c[k0 & 511u].w;
    coef = (wsum * inv) * pw;
    pre  = -(dot * inv) * pw;
}

struct ExpC {
    u64 L2E, CB, CNB, M1, C5, C4, C3, C2, C1, C0;
};

__device__ __forceinline__ void expacc(float4 v, u64& S01, u64& S23, const ExpC& K) {
    {
        u64 T = f2mul(pk(v.x, v.y), K.L2E);
        u64 Z = f2add(T, K.CB);
        u64 W = f2add(Z, K.CNB);
        u64 R = f2fma(W, K.M1, T);
        u64 P = f2fma(K.C5, R, K.C4);
        P = f2fma(P, R, K.C3);
        P = f2fma(P, R, K.C2);
        P = f2fma(P, R, K.C1);
        P = f2fma(P, R, K.C0);
        u32 zi0, zi1, pi0, pi1;
        upki(Z, zi0, zi1); upki(P, pi0, pi1);
        S01 = f2add(S01, pki(pi0 + (zi0 << 23), pi1 + (zi1 << 23)));
    }
    {
        u64 T = f2mul(pk(v.z, v.w), K.L2E);
        u64 Z = f2add(T, K.CB);
        u64 W = f2add(Z, K.CNB);
        u64 R = f2fma(W, K.M1, T);
        u64 P = f2fma(K.C5, R, K.C4);
        P = f2fma(P, R, K.C3);
        P = f2fma(P, R, K.C2);
        P = f2fma(P, R, K.C1);
        P = f2fma(P, R, K.C0);
        u32 zi0, zi1, pi0, pi1;
        upki(Z, zi0, zi1); upki(P, pi0, pi1);
        S23 = f2add(S23, pki(pi0 + (zi0 << 23), pi1 + (zi1 << 23)));
    }
}

__global__ void __launch_bounds__(TPB, 4)
loss_main(const float* __restrict__ pred,      // (B, Q, H, W)
          const float* __restrict__ tgt,       // (B, 2, H, W)
          const float* __restrict__ centers,   // (Q, 2)
          const float* __restrict__ cw,        // (Q,)
          float* __restrict__ out)
{
    __shared__ float4 s_c[QBINS];     // (cx, cy, |c|^2/2, class_weight)
    __shared__ float  s_red[TPB / 32];
    __shared__ float  s_fin[TPB];
    __shared__ bool   s_last;

    const int tid  = threadIdx.x;
    const int lane = tid & 31, wid = tid >> 5;

    for (int i = tid; i < QBINS; i += TPB) {
        float2 c = reinterpret_cast<const float2*>(centers)[i];
        float h = fmaf(0.5f * c.x, c.x, 0.5f * c.y * c.y);
        s_c[i] = make_float4(c.x, c.y, h, cw[i]);
    }
    __syncthreads();

    // ---- builder role: global warp id < NCELL builds one candidate cell ----
    const int gwarp = blockIdx.x * (TPB / 32) + wid;
    if (gwarp < NCELL) {
        build_cell(gwarp, lane, s_c);
        if (lane == 0) {
            __threadfence();
            atomicAdd(&g_ready, 1u);
        }
    }

    const int m0  = (blockIdx.x * TPB + tid) * PPT;   // four adjacent pixels
    const int b   = m0 / HWC;                         // block = 512 contiguous pixels, same b
    const int rem = m0 - b * HWC;

    const float4 av = *reinterpret_cast<const float4*>(tgt + (size_t)(2 * b)     * HWC + rem);
    const float4 bv = *reinterpret_cast<const float4*>(tgt + (size_t)(2 * b + 1) * HWC + rem);
    const float aa[4] = {av.x * 128.f, av.y * 128.f, av.z * 128.f, av.w * 128.f};
    const float bb[4] = {bv.x * 128.f, bv.y * 128.f, bv.z * 128.f, bv.w * 128.f};

    const float* gb = pred + (size_t)b * QBINS * HWC + rem;

    ExpC K;
    K.L2E = pk(1.4426950408889634f, 1.4426950408889634f);
    K.CB  = pk(12582912.0f, 12582912.0f);
    K.CNB = pk(-12582912.0f, -12582912.0f);
    K.M1  = pk(-1.0f, -1.0f);
    K.C5  = pk(1.3333558146e-3f, 1.3333558146e-3f);
    K.C4  = pk(9.6181291076e-3f, 9.6181291076e-3f);
    K.C3  = pk(5.5504108665e-2f, 5.5504108665e-2f);
    K.C2  = pk(2.4022650696e-1f, 2.4022650696e-1f);
    K.C1  = pk(6.9314718056e-1f, 6.9314718056e-1f);
    K.C0  = pk(1.0f, 1.0f);

    // ---- streaming softmax denominators, explicit 2-stage prefetch pipeline ----
    const float4* p4 = reinterpret_cast<const float4*>(gb);
    u64 S01 = 0ull, S23 = 0ull;

    float4 buf[4];
    #pragma unroll
    for (int j = 0; j < 4; ++j)
        buf[j] = __ldcs(p4 + (size_t)j * (HWC / 4));

    for (int base = 0; base <= 304; base += 4) {     // 77 iterations: q 0..307 processed
        float4 nxt[4];
        #pragma unroll
        for (int j = 0; j < 4; ++j)
            nxt[j] = __ldcs(p4 + (size_t)(base + 4 + j) * (HWC / 4));
        #pragma unroll
        for (int j = 0; j < 4; ++j)
            expacc(buf[j], S01, S23, K);
        #pragma unroll
        for (int j = 0; j < 4; ++j)
            buf[j] = nxt[j];
    }
    #pragma unroll
    for (int j = 0; j < 4; ++j)                      // q 308..311
        expacc(buf[j], S01, S23, K);
    expacc(__ldcs(p4 + (size_t)312 * (HWC / 4)), S01, S23, K);   // q 312

    float S[4];
    upkf(S01, S[0], S[1]);
    upkf(S23, S[2], S[3]);

    // ---- wait for builders (always already done: build ~1us, stream ~80us) ----
    if (tid == 0) {
        while (atomicAdd(&g_ready, 0u) < NCELL) { }
    }
    __syncthreads();

    // ---- per-pixel selection + gather (tail of pred may still be L2-resident) ----
    float part = 0.f;
    #pragma unroll
    for (int p = 0; p < 4; ++p) {
        float coef, pre;
        pixel_prep(aa[p], bb[p], gb + p, s_c, coef, pre);
        part += fmaf(coef, __logf(S[p]), pre);
    }

    // ---- deterministic block reduction ----
    #pragma unroll
    for (int o = 16; o > 0; o >>= 1)
        part += __shfl_down_sync(0xFFFFFFFFu, part, o);
    if (lane == 0) s_red[wid] = part;
    __syncthreads();

    if (tid == 0) {
        float bsum = 0.f;
        #pragma unroll
        for (int w = 0; w < TPB / 32; ++w) bsum += s_red[w];
        g_partial[blockIdx.x] = bsum;
        __threadfence();
        unsigned t = atomicAdd(&g_count, 1u);
        s_last = (t == NBLK - 1);
    }
    __syncthreads();

    // ---- last block finalizes (all blocks have passed the wait by now) ----
    if (s_last) {
        float v = 0.f;
        #pragma unroll
        for (int base = 0; base < NBLK; base += TPB)
            if (base + tid < NBLK) v += g_partial[base + tid];
        s_fin[tid] = v;
        __syncthreads();
        #pragma unroll
        for (int s = TPB / 2; s > 0; s >>= 1) {
            if (tid < s) s_fin[tid] += s_fin[tid + s];
            __syncthreads();
        }
        if (tid == 0) {
            out[0] = s_fin[0] * (1.0f / (float)MTOT);
            g_count = 0;   // reset for next graph replay
            g_ready = 0;
        }
    }
}

extern "C" void kernel_launch(void* const* d_in, const int* in_sizes, int n_in,
                              void* d_out, int out_size) {
    const float* pred    = (const float*)d_in[0];   // (32,313,96,96)
    const float* tgt     = (const float*)d_in[1];   // (32,2,96,96)
    const float* centers = (const float*)d_in[2];   // (313,2)
    const float* cw      = (const float*)d_in[3];   // (313,)
    (void)in_sizes; (void)n_in; (void)out_size;

    loss_main<<<NBLK, TPB>>>(pred, tgt, centers, cw, (float*)d_out);
}

// round 15
// speedup vs baseline: 1.2662x; 1.0109x over previous
#include <cuda_runtime.h>
#include <stdint.h>

#define QBINS 313
#define HWC   9216           // 96*96
#define MTOT  294912
#define TPB   128
#define PPT   2
#define NBLK  (MTOT / (TPB * PPT))   // 1152 = single wave at 8 CTAs/SM
#define GDIM  32
#define NCELL (GDIM * GDIM)          // 1024 cells = warps of CTAs 0..255
#define MAXC  64

__device__ unsigned short g_list[NCELL * MAXC];
__device__ int            g_cnt[NCELL];
__device__ float          g_partial[NBLK];
__device__ unsigned       g_count = 0;
__device__ unsigned       g_ready = 0;

typedef unsigned long long u64;
typedef unsigned int       u32;

// ---- packed f32x2 helpers (Blackwell FFMA2 path) ----
__device__ __forceinline__ u64 pk(float a, float b) {
    u64 r; asm("mov.b64 %0,{%1,%2};" : "=l"(r) : "f"(a), "f"(b)); return r;
}
__device__ __forceinline__ void upkf(u64 v, float& a, float& b) {
    asm("mov.b64 {%0,%1},%2;" : "=f"(a), "=f"(b) : "l"(v));
}
__device__ __forceinline__ void upki(u64 v, u32& a, u32& b) {
    asm("mov.b64 {%0,%1},%2;" : "=r"(a), "=r"(b) : "l"(v));
}
__device__ __forceinline__ u64 pki(u32 a, u32 b) {
    u64 r; asm("mov.b64 %0,{%1,%2};" : "=l"(r) : "r"(a), "r"(b)); return r;
}
__device__ __forceinline__ u64 f2mul(u64 a, u64 b) {
    u64 r; asm("mul.rn.f32x2 %0,%1,%2;" : "=l"(r) : "l"(a), "l"(b)); return r;
}
__device__ __forceinline__ u64 f2add(u64 a, u64 b) {
    u64 r; asm("add.rn.f32x2 %0,%1,%2;" : "=l"(r) : "l"(a), "l"(b)); return r;
}
__device__ __forceinline__ u64 f2fma(u64 a, u64 b, u64 c) {
    u64 r; asm("fma.rn.f32x2 %0,%1,%2,%3;" : "=l"(r) : "l"(a), "l"(b), "l"(c)); return r;
}

// sorted top-5 insert, uint keys (9 IMNMX)
__device__ __forceinline__ void ins5(u32& k0, u32& k1, u32& k2, u32& k3, u32& k4, u32 key) {
    u32 lo, hi;
    k4 = min(k4, key);
    lo = min(k3, k4); hi = max(k3, k4); k3 = lo; k4 = hi;
    lo = min(k2, k3); hi = max(k2, k3); k2 = lo; k3 = hi;
    lo = min(k1, k2); hi = max(k1, k2); k1 = lo; k2 = hi;
    lo = min(k0, k1); hi = max(k0, k1); k0 = lo; k1 = hi;
}

// sorted top-5 insert, float distances (9 FMNMX)
__device__ __forceinline__ void ins5f(float& d0, float& d1, float& d2, float& d3, float& d4, float d) {
    float lo, hi;
    d4 = fminf(d4, d);
    lo = fminf(d3, d4); hi = fmaxf(d3, d4); d3 = lo; d4 = hi;
    lo = fminf(d2, d3); hi = fmaxf(d2, d3); d2 = lo; d3 = hi;
    lo = fminf(d1, d2); hi = fmaxf(d1, d2); d1 = lo; d2 = hi;
    lo = fminf(d0, d1); hi = fmaxf(d0, d1); d0 = lo; d1 = hi;
}

// ---- builder: one warp builds one cell's candidate list (exact superset) ----
// cell side 8, half-diag r=5.657: c in top-5 of any p in cell => |c-cc| <= d5(cc)+2r.
__device__ __forceinline__ void build_cell(int cell, int lane, const float4* __restrict__ s_c) {
    const int cy = cell >> 5, cx = cell & 31;
    const float cca = -124.f + 8.f * cx;
    const float ccb = -124.f + 8.f * cy;

    float d0 = 3.4e38f, d1 = 3.4e38f, d2 = 3.4e38f, d3 = 3.4e38f, d4 = 3.4e38f;
    for (int q = lane; q < QBINS; q += 32) {
        float da = cca - s_c[q].x, db = ccb - s_c[q].y;
        ins5f(d0, d1, d2, d3, d4, fmaf(da, da, db * db));
    }
    #pragma unroll
    for (int off = 16; off > 0; off >>= 1) {
        float e0 = __shfl_xor_sync(0xFFFFFFFFu, d0, off);
        float e1 = __shfl_xor_sync(0xFFFFFFFFu, d1, off);
        float e2 = __shfl_xor_sync(0xFFFFFFFFu, d2, off);
        float e3 = __shfl_xor_sync(0xFFFFFFFFu, d3, off);
        float e4 = __shfl_xor_sync(0xFFFFFFFFu, d4, off);
        ins5f(d0, d1, d2, d3, d4, e0);
        ins5f(d0, d1, d2, d3, d4, e1);
        ins5f(d0, d1, d2, d3, d4, e2);
        ins5f(d0, d1, d2, d3, d4, e3);
        ins5f(d0, d1, d2, d3, d4, e4);
    }
    const float R  = sqrtf(d4) + 11.3138f + 0.01f;   // d5(cc) + 2r (+eps)
    const float R2 = R * R;

    int base = 0;
    for (int r = 0; r * 32 < QBINS; ++r) {
        int q = r * 32 + lane;
        bool pred = false;
        if (q < QBINS) {
            float da = cca - s_c[q].x, db = ccb - s_c[q].y;
            pred = fmaf(da, da, db * db) <= R2;
        }
        u32 mask = __ballot_sync(0xFFFFFFFFu, pred);
        int pos = base + __popc(mask & ((1u << lane) - 1u));
        if (pred && pos < MAXC) g_list[cell * MAXC + pos] = (unsigned short)q;
        base += __popc(mask);
    }
    if (lane == 0) g_cnt[cell] = min(base, MAXC);
}

// per-pixel selection + soft-encode + gather -> (coef, pre):  part = coef*log(S) + pre
__device__ __forceinline__ void pixel_prep(float a, float bb, const float* __restrict__ gb,
                                           const float4* __restrict__ s_c,
                                           float& coef, float& pre)
{
    const float up = fmaf(0.5f * a, a, fmaf(0.5f * bb, bb, 0.5f));
    int cx = min(max((int)floorf((a  + 128.f) * 0.125f), 0), GDIM - 1);
    int cy = min(max((int)floorf((bb + 128.f) * 0.125f), 0), GDIM - 1);
    int cell = cy * GDIM + cx;
    int n = g_cnt[cell];
    const unsigned short* lst = g_list + cell * MAXC;

    u32 k0 = 0xFFFFFFFFu, k1 = 0xFFFFFFFFu, k2 = 0xFFFFFFFFu,
        k3 = 0xFFFFFFFFu, k4 = 0xFFFFFFFFu;
    for (int j = 0; j < n; ++j) {
        int q = lst[j];
        float4 c = s_c[q];
        float e = fmaf(-a, c.x, fmaf(-bb, c.y, c.z)) + up;   // d2/2 + 0.5
        ins5(k0, k1, k2, k3, k4, (__float_as_uint(e) & 0xFFFFFE00u) | (u32)q);
    }

    u32 kk[5] = {k0, k1, k2, k3, k4};
    float wk[5];
    int   idx[5];
    float wsum = 0.f;
    #pragma unroll
    for (int j = 0; j < 5; ++j) {
        idx[j] = (int)(kk[j] & 511u);
        float4 c = s_c[idx[j]];
        float da = a - c.x;
        float db = bb - c.y;
        float d2 = fmaf(da, da, db * db);
        float w  = __expf(-0.02f * d2);     // exp(-d2/(2*sigma^2)), sigma=5
        wk[j] = w;
        wsum += w;
    }
    float inv = 1.0f / (wsum + 1e-8f);
    float dot = 0.f;
    #pragma unroll
    for (int j = 0; j < 5; ++j) {
        float x = __ldg(gb + (size_t)idx[j] * HWC);
        dot = fmaf(wk[j], x, dot);
    }
    float pw = s_c[k0 & 511u].w;
    coef = (wsum * inv) * pw;
    pre  = -(dot * inv) * pw;
}

__global__ void __launch_bounds__(TPB, 8)
loss_main(const float* __restrict__ pred,      // (B, Q, H, W)
          const float* __restrict__ tgt,       // (B, 2, H, W)
          const float* __restrict__ centers,   // (Q, 2)
          const float* __restrict__ cw,        // (Q,)
          float* __restrict__ out)
{
    __shared__ float4 s_c[QBINS];     // (cx, cy, |c|^2/2, class_weight)
    __shared__ float  s_red[TPB / 32];
    __shared__ float  s_fin[TPB];
    __shared__ bool   s_last;

    const int tid  = threadIdx.x;
    const int lane = tid & 31, wid = tid >> 5;

    for (int i = tid; i < QBINS; i += TPB) {
        float2 c = reinterpret_cast<const float2*>(centers)[i];
        float h = fmaf(0.5f * c.x, c.x, 0.5f * c.y * c.y);
        s_c[i] = make_float4(c.x, c.y, h, cw[i]);
    }
    __syncthreads();

    // ---- builder role: global warp id < NCELL builds one candidate cell ----
    const int gwarp = blockIdx.x * (TPB / 32) + wid;
    if (gwarp < NCELL) {
        build_cell(gwarp, lane, s_c);
        if (lane == 0) {
            __threadfence();
            atomicAdd(&g_ready, 1u);
        }
    }

    const int m0  = (blockIdx.x * TPB + tid) * PPT;   // two adjacent pixels
    const int b   = m0 / HWC;                         // block = 256 contiguous pixels, same b
    const int rem = m0 - b * HWC;

    const float2 av = *reinterpret_cast<const float2*>(tgt + (size_t)(2 * b)     * HWC + rem);
    const float2 bv = *reinterpret_cast<const float2*>(tgt + (size_t)(2 * b + 1) * HWC + rem);
    const float a0 = av.x * 128.f, a1 = av.y * 128.f;
    const float b0 = bv.x * 128.f, b1 = bv.y * 128.f;

    const float* gb = pred + (size_t)b * QBINS * HWC + rem;
    const float2* p2 = reinterpret_cast<const float2*>(gb);

    // exp2 constants (degree-5 — the validated fast schedule)
    const u64 L2E = pk(1.4426950408889634f, 1.4426950408889634f);
    const u64 CB  = pk(12582912.0f, 12582912.0f);
    const u64 CNB = pk(-12582912.0f, -12582912.0f);
    const u64 M1  = pk(-1.0f, -1.0f);
    const u64 C5  = pk(1.3333558146e-3f, 1.3333558146e-3f);
    const u64 C4  = pk(9.6181291076e-3f, 9.6181291076e-3f);
    const u64 C3  = pk(5.5504108665e-2f, 5.5504108665e-2f);
    const u64 C2  = pk(2.4022650696e-1f, 2.4022650696e-1f);
    const u64 C1  = pk(6.9314718056e-1f, 6.9314718056e-1f);
    const u64 C0  = pk(1.0f, 1.0f);

    // ---- pure streaming softmax denominators (unroll 8, float2 — R6 shape) ----
    u64 S01 = 0ull;
    #pragma unroll 8
    for (int q = 0; q < QBINS; ++q) {
        float2 v = __ldcs(p2 + (size_t)q * (HWC / 2));
        u64 T = f2mul(pk(v.x, v.y), L2E);
        u64 Z = f2add(T, CB);
        u64 W = f2add(Z, CNB);               // rint(t)
        u64 R = f2fma(W, M1, T);             // t - rint(t), in [-0.5,0.5]
        u64 P = f2fma(C5, R, C4);
        P = f2fma(P, R, C3);
        P = f2fma(P, R, C2);
        P = f2fma(P, R, C1);
        P = f2fma(P, R, C0);
        u32 zi0, zi1, pi0, pi1;
        upki(Z, zi0, zi1); upki(P, pi0, pi1);
        S01 = f2add(S01, pki(pi0 + (zi0 << 23), pi1 + (zi1 << 23)));
    }
    float S0, S1;
    upkf(S01, S0, S1);

    // ---- wait for builders (always done: build ~1us vs stream ~70us) ----
    if (tid == 0) {
        while (atomicAdd(&g_ready, 0u) < NCELL) { }
    }
    __syncthreads();

    // ---- selection + gather after the stream (tail of pred still L2-resident) ----
    float coef0, pre0, coef1, pre1;
    pixel_prep(a0, b0, gb,     s_c, coef0, pre0);
    pixel_prep(a1, b1, gb + 1, s_c, coef1, pre1);

    float part = fmaf(coef0, __logf(S0), pre0) + fmaf(coef1, __logf(S1), pre1);

    // ---- deterministic block reduction ----
    #pragma unroll
    for (int o = 16; o > 0; o >>= 1)
        part += __shfl_down_sync(0xFFFFFFFFu, part, o);
    if (lane == 0) s_red[wid] = part;
    __syncthreads();

    if (tid == 0) {
        float bsum = 0.f;
        #pragma unroll
        for (int w = 0; w < TPB / 32; ++w) bsum += s_red[w];
        g_partial[blockIdx.x] = bsum;
        __threadfence();
        unsigned t = atomicAdd(&g_count, 1u);
        s_last = (t == NBLK - 1);
    }
    __syncthreads();

    // ---- last block finalizes ----
    if (s_last) {
        float v = 0.f;
        #pragma unroll
        for (int base = 0; base < NBLK; base += TPB)
            v += g_partial[base + tid];
        s_fin[tid] = v;
        __syncthreads();
        #pragma unroll
        for (int s = TPB / 2; s > 0; s >>= 1) {
            if (tid < s) s_fin[tid] += s_fin[tid + s];
            __syncthreads();
        }
        if (tid == 0) {
            out[0] = s_fin[0] * (1.0f / (float)MTOT);
            g_count = 0;   // reset for next graph replay
            g_ready = 0;
        }
    }
}

extern "C" void kernel_launch(void* const* d_in, const int* in_sizes, int n_in,
                              void* d_out, int out_size) {
    const float* pred    = (const float*)d_in[0];   // (32,313,96,96)
    const float* tgt     = (const float*)d_in[1];   // (32,2,96,96)
    const float* centers = (const float*)d_in[2];   // (313,2)
    const float* cw      = (const float*)d_in[3];   // (313,)
    (void)in_sizes; (void)n_in; (void)out_size;

    loss_main<<<NBLK, TPB>>>(pred, tgt, centers, cw, (float*)d_out);
}